// round 1
// baseline (speedup 1.0000x reference)
#include <cuda_runtime.h>
#include <cstdint>

// ---------------------------------------------------------------------------
// AlignedMPNN: B=8, N=256, F=128, D=128
// Inputs (metadata order):
//  0 node_fts  [8,256,128]   f32
//  1 edge_fts  [8,256,256,128] f32
//  2 graph_fts [8,128]       f32   (unused)
//  3 adj_mat   [8,256,256]   i32
//  4 hidden    [8,256,128]   f32
//  5 e_hidden  [8,256,256,128] f32
//  6 We  [256,128]  7 be  [128]
//  8 W_m1[256,128]  9 b_m1[128]
// 10 W_m2[256,128] 11 b_m2[128]
// 12 W_o1[256,128] 13 b_o1[128]
// 14 W_o2[128,128] 15 b_o2[128]
// Output: ret [8,256,128] (262144 f32) followed by et [8,256,256,128] (8388608 f32)
// ---------------------------------------------------------------------------

#define Bq 8
#define Nn 256
#define Ff 128
#define Dd 128
#define M_ET (Bq * Nn * Nn)          // 524288
#define NROWS (Bq * (Nn + 1))        // 2056

// scratch (no cudaMalloc allowed)
__device__ float g_msg1[NROWS * Dd];
__device__ float g_msg2[NROWS * Dd];
__device__ float g_o1[NROWS * Dd];
__device__ float g_msgsout[Bq * Nn * Dd];

// ===========================================================================
// Kernel 1: et GEMM  C[M,128] = A1[M,128] @ We[0:128,:] + A2[M,128] @ We[128:256,:] + be
// BM=128, BN=128, BK=16, 256 threads, 8x8 per thread, f32x2 packed FMA.
// ===========================================================================
#define BM 128
#define BN 128
#define BK 16

__global__ __launch_bounds__(256, 2)
void et_gemm_kernel(const float* __restrict__ A1,
                    const float* __restrict__ A2,
                    const float* __restrict__ W,     // [256,128]
                    const float* __restrict__ bias,  // [128]
                    float* __restrict__ C)           // [M,128]
{
    __shared__ float As[BK][BM];
    __shared__ float Bs[BK][BN];

    const int tid = threadIdx.x;
    const int m0  = blockIdx.x * BM;
    const int tx  = tid & 15;   // 0..15 -> 8 cols each
    const int ty  = tid >> 4;   // 0..15 -> 8 rows each

    unsigned long long acc[8][4];
#pragma unroll
    for (int m = 0; m < 8; ++m)
#pragma unroll
        for (int p = 0; p < 4; ++p) acc[m][p] = 0ull;

#pragma unroll 1
    for (int kt = 0; kt < 16; ++kt) {
        const float* Asrc = (kt < 8) ? A1 : A2;
        const int kofs = (kt < 8) ? kt * 16 : (kt - 8) * 16;

        // Load A tile: 128 rows x 16 k-cols = 512 float4, 2 per thread.
#pragma unroll
        for (int h = 0; h < 2; ++h) {
            int f  = tid + h * 256;
            int m  = f >> 2;          // 0..127
            int kq = (f & 3) * 4;     // 0,4,8,12
            float4 v = *(const float4*)&Asrc[(size_t)(m0 + m) * 128 + kofs + kq];
            As[kq + 0][m] = v.x;
            As[kq + 1][m] = v.y;
            As[kq + 2][m] = v.z;
            As[kq + 3][m] = v.w;
        }
        // Load B tile: 16 rows x 128 cols = 512 float4, 2 per thread.
#pragma unroll
        for (int h = 0; h < 2; ++h) {
            int f  = tid + h * 256;
            int kr = f >> 5;          // 0..15
            int nq = (f & 31) * 4;    // 0..124
            *(float4*)&Bs[kr][nq] = *(const float4*)&W[(kt * 16 + kr) * 128 + nq];
        }
        __syncthreads();

#pragma unroll
        for (int k = 0; k < BK; ++k) {
            float4 a0 = *(const float4*)&As[k][ty * 8];
            float4 a1 = *(const float4*)&As[k][ty * 8 + 4];
            ulonglong2 b0 = *(const ulonglong2*)&Bs[k][tx * 8];
            ulonglong2 b1 = *(const ulonglong2*)&Bs[k][tx * 8 + 4];
            unsigned long long bv[4] = {b0.x, b0.y, b1.x, b1.y};
            float am[8] = {a0.x, a0.y, a0.z, a0.w, a1.x, a1.y, a1.z, a1.w};
#pragma unroll
            for (int m = 0; m < 8; ++m) {
                unsigned long long av;
                asm("mov.b64 %0, {%1, %1};" : "=l"(av) : "r"(__float_as_uint(am[m])));
#pragma unroll
                for (int p = 0; p < 4; ++p) {
                    asm("fma.rn.f32x2 %0, %1, %2, %0;"
                        : "+l"(acc[m][p]) : "l"(av), "l"(bv[p]));
                }
            }
        }
        __syncthreads();
    }

    // Epilogue: unpack, add bias, store.
    const int n0 = tx * 8;
    float bvals[8];
#pragma unroll
    for (int p = 0; p < 8; ++p) bvals[p] = bias[n0 + p];

#pragma unroll
    for (int m = 0; m < 8; ++m) {
        float out[8];
#pragma unroll
        for (int p = 0; p < 4; ++p) {
            unsigned int lo, hi;
            asm("mov.b64 {%0, %1}, %2;" : "=r"(lo), "=r"(hi) : "l"(acc[m][p]));
            out[2 * p + 0] = __uint_as_float(lo) + bvals[2 * p + 0];
            out[2 * p + 1] = __uint_as_float(hi) + bvals[2 * p + 1];
        }
        size_t row = (size_t)(m0 + ty * 8 + m);
        *(float4*)&C[row * 128 + n0]     = make_float4(out[0], out[1], out[2], out[3]);
        *(float4*)&C[row * 128 + n0 + 4] = make_float4(out[4], out[5], out[6], out[7]);
    }
}

// ===========================================================================
// Kernel 2: msg1/msg2/o1 = nt @ {W_m1,W_m2,W_o1} + bias.  nt row = concat(node,hidden),
// virtual row (i==256) is zeros. 8 rows / block, 257 blocks, 128 threads.
// ===========================================================================
__global__ __launch_bounds__(128)
void msgs_gemm_kernel(const float* __restrict__ node,
                      const float* __restrict__ hidden,
                      const float* __restrict__ Wm1, const float* __restrict__ bm1,
                      const float* __restrict__ Wm2, const float* __restrict__ bm2,
                      const float* __restrict__ Wo1, const float* __restrict__ bo1)
{
    __shared__ float s[8][2 * Ff];
    const int r0  = blockIdx.x * 8;
    const int tid = threadIdx.x;

#pragma unroll
    for (int r = 0; r < 8; ++r) {
        int row = r0 + r;                 // < 2056 always (257*8)
        int b = row / (Nn + 1);
        int i = row % (Nn + 1);
        float v1 = 0.f, v2 = 0.f;
        if (i < Nn) {
            v1 = node[(b * Nn + i) * Ff + tid];
            v2 = hidden[(b * Nn + i) * Ff + tid];
        }
        s[r][tid]      = v1;
        s[r][Ff + tid] = v2;
    }
    __syncthreads();

    float a1[8], a2[8], a3[8];
    float bb1 = bm1[tid], bb2 = bm2[tid], bb3 = bo1[tid];
#pragma unroll
    for (int r = 0; r < 8; ++r) { a1[r] = bb1; a2[r] = bb2; a3[r] = bb3; }

    for (int k = 0; k < 2 * Ff; ++k) {
        float w1 = Wm1[k * Dd + tid];
        float w2 = Wm2[k * Dd + tid];
        float w3 = Wo1[k * Dd + tid];
#pragma unroll
        for (int r = 0; r < 8; ++r) {
            float sv = s[r][k];
            a1[r] = fmaf(sv, w1, a1[r]);
            a2[r] = fmaf(sv, w2, a2[r]);
            a3[r] = fmaf(sv, w3, a3[r]);
        }
    }
#pragma unroll
    for (int r = 0; r < 8; ++r) {
        int row = r0 + r;
        g_msg1[row * Dd + tid] = a1[r];
        g_msg2[row * Dd + tid] = a2[r];
        g_o1[row * Dd + tid]   = a3[r];
    }
}

// ===========================================================================
// Kernel 3: masked max over senders + add msg1.
// block = (b, j), 2048 blocks, 128 threads (one per d).
// msgsout[b,j,d] = msg1[b,j,d] + max( msg2[b,256,d], max_{i<N, adj[b,i,j]>0} msg2[b,i,d] )
// ===========================================================================
__global__ __launch_bounds__(128)
void maxred_kernel(const int* __restrict__ adj)
{
    __shared__ int col[Nn];
    const int bj  = blockIdx.x;
    const int b   = bj >> 8;
    const int j   = bj & 255;
    const int tid = threadIdx.x;

    col[tid]       = adj[((b * Nn) + tid) * Nn + j];
    col[tid + 128] = adj[((b * Nn) + tid + 128) * Nn + j];
    __syncthreads();

    // virtual node (i == N) is always connected
    float m = g_msg2[(b * (Nn + 1) + Nn) * Dd + tid];
#pragma unroll 4
    for (int i = 0; i < Nn; ++i) {
        if (col[i] > 0) {
            m = fmaxf(m, g_msg2[(b * (Nn + 1) + i) * Dd + tid]);
        }
    }
    g_msgsout[bj * Dd + tid] = g_msg1[(b * (Nn + 1) + j) * Dd + tid] + m;
}

// ===========================================================================
// Kernel 4: ret = o1 + msgsout @ W_o2 + b_o2.   8 rows/block, 256 blocks.
// ===========================================================================
__global__ __launch_bounds__(128)
void final_gemm_kernel(const float* __restrict__ Wo2,
                       const float* __restrict__ bo2,
                       float* __restrict__ out)   // [B*N,128]
{
    __shared__ float s[8][Dd];
    const int r0  = blockIdx.x * 8;
    const int tid = threadIdx.x;

#pragma unroll
    for (int r = 0; r < 8; ++r) s[r][tid] = g_msgsout[(r0 + r) * Dd + tid];
    __syncthreads();

    float acc[8];
    float bb = bo2[tid];
#pragma unroll
    for (int r = 0; r < 8; ++r) {
        int row = r0 + r;           // = b*256 + j
        int b = row >> 8, j = row & 255;
        acc[r] = g_o1[(b * (Nn + 1) + j) * Dd + tid] + bb;
    }
    for (int k = 0; k < Dd; ++k) {
        float w = Wo2[k * Dd + tid];
#pragma unroll
        for (int r = 0; r < 8; ++r) acc[r] = fmaf(s[r][k], w, acc[r]);
    }
#pragma unroll
    for (int r = 0; r < 8; ++r) out[(r0 + r) * Dd + tid] = acc[r];
}

// ===========================================================================
extern "C" void kernel_launch(void* const* d_in, const int* in_sizes, int n_in,
                              void* d_out, int out_size)
{
    const float* node_fts = (const float*)d_in[0];
    const float* edge_fts = (const float*)d_in[1];
    // d_in[2] = graph_fts (unused)
    const int*   adj_mat  = (const int*)d_in[3];
    const float* hidden   = (const float*)d_in[4];
    const float* e_hidden = (const float*)d_in[5];
    const float* We   = (const float*)d_in[6];
    const float* be   = (const float*)d_in[7];
    const float* W_m1 = (const float*)d_in[8];
    const float* b_m1 = (const float*)d_in[9];
    const float* W_m2 = (const float*)d_in[10];
    const float* b_m2 = (const float*)d_in[11];
    const float* W_o1 = (const float*)d_in[12];
    const float* b_o1 = (const float*)d_in[13];
    const float* W_o2 = (const float*)d_in[14];
    const float* b_o2 = (const float*)d_in[15];

    float* ret_out = (float*)d_out;                    // [8*256*128]
    float* et_out  = (float*)d_out + Bq * Nn * Dd;     // [8*256*256*128]

    // MPNN chain (tiny)
    msgs_gemm_kernel<<<NROWS / 8, 128>>>(node_fts, hidden,
                                         W_m1, b_m1, W_m2, b_m2, W_o1, b_o1);
    maxred_kernel<<<Bq * Nn, 128>>>(adj_mat);
    final_gemm_kernel<<<(Bq * Nn) / 8, 128>>>(W_o2, b_o2, ret_out);

    // Big et GEMM
    et_gemm_kernel<<<M_ET / BM, 256>>>(edge_fts, e_hidden, We, be, et_out);
}

// round 3
// speedup vs baseline: 1.7598x; 1.7598x over previous
#include <cuda_runtime.h>
#include <cstdint>

// ---------------------------------------------------------------------------
// AlignedMPNN: B=8, N=256, F=128, D=128
// Output: ret [8,256,128] followed by et [8,256,256,128]
// ---------------------------------------------------------------------------

#define Bq 8
#define Nn 256
#define Ff 128
#define Dd 128
#define M_ET (Bq * Nn * Nn)          // 524288
#define NROWS (Bq * (Nn + 1))        // 2056
#define N_TILES (M_ET / 128)         // 4096

// scratch for MPNN chain
__device__ float g_msg1[NROWS * Dd];
__device__ float g_msg2[NROWS * Dd];
__device__ float g_o1[NROWS * Dd];
__device__ float g_msgsout[Bq * Nn * Dd];

// ===========================================================================
// helpers
// ===========================================================================
__device__ __forceinline__ uint32_t smem_u32_of(const void* p) {
    uint32_t a;
    asm("{ .reg .u64 t; cvta.to.shared.u64 t, %1; cvt.u32.u64 %0, t; }" : "=r"(a) : "l"(p));
    return a;
}

#define STS128(a0, a1, a2, a3, addr) \
    asm volatile("st.shared.v4.b32 [%0], {%1, %2, %3, %4};" :: "r"(addr), "r"(a0), "r"(a1), "r"(a2), "r"(a3) : "memory")

#define LDSM4(r, addr) \
    asm volatile("ldmatrix.sync.aligned.m8n8.x4.shared.b16 {%0,%1,%2,%3}, [%4];" \
        : "=r"((r)[0]), "=r"((r)[1]), "=r"((r)[2]), "=r"((r)[3]) : "r"(addr))

#define LDSM2(r, addr) \
    asm volatile("ldmatrix.sync.aligned.m8n8.x2.shared.b16 {%0,%1}, [%2];" \
        : "=r"((r)[0]), "=r"((r)[1]) : "r"(addr))

#define MMA_BF16(d, a, b) \
    asm volatile("mma.sync.aligned.m16n8k16.row.col.f32.bf16.bf16.f32 " \
        "{%0,%1,%2,%3}, {%4,%5,%6,%7}, {%8,%9}, {%0,%1,%2,%3};" \
        : "+f"((d)[0]), "+f"((d)[1]), "+f"((d)[2]), "+f"((d)[3]) \
        : "r"((a)[0]), "r"((a)[1]), "r"((a)[2]), "r"((a)[3]), "r"((b)[0]), "r"((b)[1]))

// bf16 two-term split of a pair of f32: packed hi (bf16x2) and lo (bf16x2)
__device__ __forceinline__ void split2(float x0, float x1, uint32_t& hi2, uint32_t& lo2) {
    asm("cvt.rn.bf16x2.f32 %0, %1, %2;" : "=r"(hi2) : "f"(x1), "f"(x0));
    float h0 = __uint_as_float(hi2 << 16);
    float h1 = __uint_as_float(hi2 & 0xffff0000u);
    float r0 = x0 - h0;
    float r1 = x1 - h1;
    asm("cvt.rn.bf16x2.f32 %0, %1, %2;" : "=r"(lo2) : "f"(r1), "f"(r0));
}

// ===========================================================================
// et GEMM: C[M,128] = A1[M,0:128k] @ W[0:128,:] + A2[M,0:128k] @ W[128:256,:] + be
// mma.sync bf16 3-term split, persistent grid.
//
// smem layout:
//   W tiles: 16 chunks x {hi,lo}: chunk c hi at c*12288, lo at c*12288+6144.
//            each: [128 n][48B] rows, 2x16B k-units used per row (k=c*16+ku*8+j).
//   A tiles: OFF_A + buf*12288 + {0 hi | 6144 lo}: [128 m][48B], 2x16B k-units.
// ===========================================================================
#define OFF_A   196608
#define SMEM_ET 221184

__global__ __launch_bounds__(256, 1)
void et_mma_kernel(const float* __restrict__ A1,
                   const float* __restrict__ A2,
                   const float* __restrict__ W,     // [256,128] f32
                   const float* __restrict__ bias,  // [128]
                   float* __restrict__ C)           // [M,128]
{
    extern __shared__ char smem[];
    const uint32_t sb = smem_u32_of(smem);
    const int tid   = threadIdx.x;
    const int lane  = tid & 31;
    const int wid   = tid >> 5;
    const int warpM = wid >> 2;      // 0..1  -> rows warpM*64
    const int warpN = wid & 3;       // 0..3  -> cols warpN*32

    // ---- one-time W conversion into resident smem (bf16 hi/lo, [n][k]) ----
    {
        const int n  = tid & 127;
        const int ks = (tid >> 7) * 16;
        for (int u = 0; u < 16; ++u) {
            const int kk = ks + u;                 // 8-k group index 0..31
            float w[8];
#pragma unroll
            for (int j = 0; j < 8; ++j) w[j] = W[(kk * 8 + j) * 128 + n];
            uint32_t h[4], l[4];
#pragma unroll
            for (int j = 0; j < 4; ++j) split2(w[2 * j], w[2 * j + 1], h[j], l[j]);
            const uint32_t a = sb + (uint32_t)((kk >> 1) * 12288 + n * 48 + (kk & 1) * 16);
            STS128(h[0], h[1], h[2], h[3], a);
            STS128(l[0], l[1], l[2], l[3], a + 6144);
        }
    }

    // ---- per-thread invariant addressing ----
    // ldmatrix A (x4): mats (m0-7,k0-7),(m8-15,k0-7),(m0-7,k8-15),(m8-15,k8-15)
    const int mat   = lane >> 3;
    const int mi    = lane & 7;
    const int m_off = (mat & 1) * 8 + mi;
    const int ah    = mat >> 1;
    uint32_t aoff[4];
#pragma unroll
    for (int mt = 0; mt < 4; ++mt)
        aoff[mt] = (uint32_t)((warpM * 64 + mt * 16 + m_off) * 48 + ah * 16);

    // ldmatrix B (x2): mats (k0-7 x n0-7),(k8-15 x n0-7); storage [n][k-unit]
    const int ls = lane & 15;
    uint32_t boff[4];
#pragma unroll
    for (int nt = 0; nt < 4; ++nt)
        boff[nt] = (uint32_t)((warpN * 32 + nt * 8 + (ls & 7)) * 48 + (ls >> 3) * 16);

    float2 biasv[4];
#pragma unroll
    for (int nt = 0; nt < 4; ++nt)
        biasv[nt] = *(const float2*)&bias[warpN * 32 + nt * 8 + (lane & 3) * 2];

    // A global-load + convert mapping: 2 threads per row
    const int row  = tid >> 1;
    const int half = tid & 1;
    const uint32_t soff = (uint32_t)(row * 48 + half * 16);
    const int goff = row * 128 + half * 8;

    __syncthreads();

    int tile = blockIdx.x;
    float4 v0, v1;
    if (tile < N_TILES) {
        const float* p = A1 + (size_t)tile * 16384 + goff;
        v0 = *(const float4*)p;
        v1 = *(const float4*)(p + 4);
    }

    while (tile < N_TILES) {
        float acc[4][4][4];
#pragma unroll
        for (int mt = 0; mt < 4; ++mt)
#pragma unroll
            for (int nt = 0; nt < 4; ++nt) {
                acc[mt][nt][0] = biasv[nt].x; acc[mt][nt][1] = biasv[nt].y;
                acc[mt][nt][2] = biasv[nt].x; acc[mt][nt][3] = biasv[nt].y;
            }

#pragma unroll 1
        for (int c = 0; c < 16; ++c) {
            const int buf = c & 1;

            // convert prefetched chunk -> smem buf
            uint32_t h0, h1, h2, h3, l0, l1, l2, l3;
            split2(v0.x, v0.y, h0, l0);
            split2(v0.z, v0.w, h1, l1);
            split2(v1.x, v1.y, h2, l2);
            split2(v1.z, v1.w, h3, l3);
            const uint32_t sa = sb + OFF_A + buf * 12288 + soff;
            STS128(h0, h1, h2, h3, sa);
            STS128(l0, l1, l2, l3, sa + 6144);
            __syncthreads();

            // prefetch next chunk (possibly next tile's chunk 0)
            {
                int ntile = tile, nc = c + 1;
                if (nc == 16) { ntile += gridDim.x; nc = 0; }
                if (ntile < N_TILES) {
                    const float* base = (nc < 8) ? A1 : A2;
                    const float* p = base + (size_t)ntile * 16384 + goff + (nc & 7) * 16;
                    v0 = *(const float4*)p;
                    v1 = *(const float4*)(p + 4);
                }
            }

            // compute: hh, lh, hl terms
            const uint32_t wb = sb + (uint32_t)(c * 12288);
            const uint32_t ab = sb + OFF_A + buf * 12288;
            uint32_t Ah[4][4], Al[4][4], Bv[4][2];
#pragma unroll
            for (int mt = 0; mt < 4; ++mt) LDSM4(Ah[mt], ab + aoff[mt]);
#pragma unroll
            for (int nt = 0; nt < 4; ++nt) LDSM2(Bv[nt], wb + boff[nt]);
#pragma unroll
            for (int mt = 0; mt < 4; ++mt)
#pragma unroll
                for (int nt = 0; nt < 4; ++nt) MMA_BF16(acc[mt][nt], Ah[mt], Bv[nt]);
#pragma unroll
            for (int mt = 0; mt < 4; ++mt) LDSM4(Al[mt], ab + 6144 + aoff[mt]);
#pragma unroll
            for (int mt = 0; mt < 4; ++mt)
#pragma unroll
                for (int nt = 0; nt < 4; ++nt) MMA_BF16(acc[mt][nt], Al[mt], Bv[nt]);
#pragma unroll
            for (int nt = 0; nt < 4; ++nt) LDSM2(Bv[nt], wb + 6144 + boff[nt]);
#pragma unroll
            for (int mt = 0; mt < 4; ++mt)
#pragma unroll
                for (int nt = 0; nt < 4; ++nt) MMA_BF16(acc[mt][nt], Ah[mt], Bv[nt]);
        }

        // epilogue: direct STG (32B-sector aligned float2 stores)
        const size_t m0 = (size_t)tile * 128;
#pragma unroll
        for (int mt = 0; mt < 4; ++mt) {
            const size_t r0 = m0 + warpM * 64 + mt * 16 + (lane >> 2);
#pragma unroll
            for (int nt = 0; nt < 4; ++nt) {
                const int col = warpN * 32 + nt * 8 + (lane & 3) * 2;
                *(float2*)&C[r0 * 128 + col]       = make_float2(acc[mt][nt][0], acc[mt][nt][1]);
                *(float2*)&C[(r0 + 8) * 128 + col] = make_float2(acc[mt][nt][2], acc[mt][nt][3]);
            }
        }
        tile += gridDim.x;
    }
}

// ===========================================================================
// Kernel 2: msg1/msg2/o1 = nt @ {W_m1,W_m2,W_o1} + bias
// ===========================================================================
__global__ __launch_bounds__(128)
void msgs_gemm_kernel(const float* __restrict__ node,
                      const float* __restrict__ hidden,
                      const float* __restrict__ Wm1, const float* __restrict__ bm1,
                      const float* __restrict__ Wm2, const float* __restrict__ bm2,
                      const float* __restrict__ Wo1, const float* __restrict__ bo1)
{
    __shared__ float s[8][2 * Ff];
    const int r0  = blockIdx.x * 8;
    const int tid = threadIdx.x;

#pragma unroll
    for (int r = 0; r < 8; ++r) {
        int rowi = r0 + r;
        int b = rowi / (Nn + 1);
        int i = rowi % (Nn + 1);
        float v1 = 0.f, v2 = 0.f;
        if (i < Nn) {
            v1 = node[(b * Nn + i) * Ff + tid];
            v2 = hidden[(b * Nn + i) * Ff + tid];
        }
        s[r][tid]      = v1;
        s[r][Ff + tid] = v2;
    }
    __syncthreads();

    float a1[8], a2[8], a3[8];
    float bb1 = bm1[tid], bb2 = bm2[tid], bb3 = bo1[tid];
#pragma unroll
    for (int r = 0; r < 8; ++r) { a1[r] = bb1; a2[r] = bb2; a3[r] = bb3; }

    for (int k = 0; k < 2 * Ff; ++k) {
        float w1 = Wm1[k * Dd + tid];
        float w2 = Wm2[k * Dd + tid];
        float w3 = Wo1[k * Dd + tid];
#pragma unroll
        for (int r = 0; r < 8; ++r) {
            float sv = s[r][k];
            a1[r] = fmaf(sv, w1, a1[r]);
            a2[r] = fmaf(sv, w2, a2[r]);
            a3[r] = fmaf(sv, w3, a3[r]);
        }
    }
#pragma unroll
    for (int r = 0; r < 8; ++r) {
        int rowi = r0 + r;
        g_msg1[rowi * Dd + tid] = a1[r];
        g_msg2[rowi * Dd + tid] = a2[r];
        g_o1[rowi * Dd + tid]   = a3[r];
    }
}

// ===========================================================================
// Kernel 3: masked max over senders + add msg1
// ===========================================================================
__global__ __launch_bounds__(128)
void maxred_kernel(const int* __restrict__ adj)
{
    __shared__ int col[Nn];
    const int bj  = blockIdx.x;
    const int b   = bj >> 8;
    const int j   = bj & 255;
    const int tid = threadIdx.x;

    col[tid]       = adj[((b * Nn) + tid) * Nn + j];
    col[tid + 128] = adj[((b * Nn) + tid + 128) * Nn + j];
    __syncthreads();

    float m = g_msg2[(b * (Nn + 1) + Nn) * Dd + tid];  // virtual node always connected
#pragma unroll 4
    for (int i = 0; i < Nn; ++i) {
        if (col[i] > 0) {
            m = fmaxf(m, g_msg2[(b * (Nn + 1) + i) * Dd + tid]);
        }
    }
    g_msgsout[bj * Dd + tid] = g_msg1[(b * (Nn + 1) + j) * Dd + tid] + m;
}

// ===========================================================================
// Kernel 4: ret = o1 + msgsout @ W_o2 + b_o2
// ===========================================================================
__global__ __launch_bounds__(128)
void final_gemm_kernel(const float* __restrict__ Wo2,
                       const float* __restrict__ bo2,
                       float* __restrict__ out)
{
    __shared__ float s[8][Dd];
    const int r0  = blockIdx.x * 8;
    const int tid = threadIdx.x;

#pragma unroll
    for (int r = 0; r < 8; ++r) s[r][tid] = g_msgsout[(r0 + r) * Dd + tid];
    __syncthreads();

    float acc[8];
    float bb = bo2[tid];
#pragma unroll
    for (int r = 0; r < 8; ++r) {
        int rowi = r0 + r;
        int b = rowi >> 8, j = rowi & 255;
        acc[r] = g_o1[(b * (Nn + 1) + j) * Dd + tid] + bb;
    }
    for (int k = 0; k < Dd; ++k) {
        float w = Wo2[k * Dd + tid];
#pragma unroll
        for (int r = 0; r < 8; ++r) acc[r] = fmaf(s[r][k], w, acc[r]);
    }
#pragma unroll
    for (int r = 0; r < 8; ++r) out[(r0 + r) * Dd + tid] = acc[r];
}

// ===========================================================================
extern "C" void kernel_launch(void* const* d_in, const int* in_sizes, int n_in,
                              void* d_out, int out_size)
{
    const float* node_fts = (const float*)d_in[0];
    const float* edge_fts = (const float*)d_in[1];
    const int*   adj_mat  = (const int*)d_in[3];
    const float* hidden   = (const float*)d_in[4];
    const float* e_hidden = (const float*)d_in[5];
    const float* We   = (const float*)d_in[6];
    const float* be   = (const float*)d_in[7];
    const float* W_m1 = (const float*)d_in[8];
    const float* b_m1 = (const float*)d_in[9];
    const float* W_m2 = (const float*)d_in[10];
    const float* b_m2 = (const float*)d_in[11];
    const float* W_o1 = (const float*)d_in[12];
    const float* b_o1 = (const float*)d_in[13];
    const float* W_o2 = (const float*)d_in[14];
    const float* b_o2 = (const float*)d_in[15];

    float* ret_out = (float*)d_out;
    float* et_out  = (float*)d_out + Bq * Nn * Dd;

    cudaFuncSetAttribute(et_mma_kernel, cudaFuncAttributeMaxDynamicSharedMemorySize, SMEM_ET);

    // MPNN chain (small)
    msgs_gemm_kernel<<<NROWS / 8, 128>>>(node_fts, hidden,
                                         W_m1, b_m1, W_m2, b_m2, W_o1, b_o1);
    maxred_kernel<<<Bq * Nn, 128>>>(adj_mat);
    final_gemm_kernel<<<(Bq * Nn) / 8, 128>>>(W_o2, b_o2, ret_out);

    // Big et GEMM on tensor cores (persistent, mma.sync bf16-split)
    et_mma_kernel<<<148, 256, SMEM_ET>>>(edge_fts, e_hidden, We, be, et_out);
}